// round 8
// baseline (speedup 1.0000x reference)
#include <cuda_runtime.h>
#include <math.h>
#include <stdint.h>

#define kB 64
#define kT 128
#define kU 256
#define kV 16000
#define kG 1024   /* 4*U */
#define kM 8192   /* B*T */

// ---------------- scratch (device globals; no allocation allowed) ----------
__device__ __align__(16) float g_Z0x[kT * kB * kG];
__device__ __align__(16) float g_H0[(kT + 1) * kB * kU];
__device__ __align__(16) float g_H1[(kT + 1) * kB * kU];
__device__ float g_S[kM];
__device__ float g_TL[kM];
__device__ unsigned g_bar[4];

__device__ __forceinline__ float sigmoidf_(float x) { return 1.f / (1.f + __expf(-x)); }

__device__ __forceinline__ uint32_t f2tf32(float x) {
    uint32_t u; asm("cvt.rna.tf32.f32 %0, %1;" : "=r"(u) : "f"(x)); return u;
}

__device__ __forceinline__ void mma_tf32(float* C,
    uint32_t a0, uint32_t a1, uint32_t a2, uint32_t a3, uint32_t b0, uint32_t b1) {
    asm volatile(
        "mma.sync.aligned.m16n8k8.row.col.f32.tf32.tf32.f32 "
        "{%0,%1,%2,%3}, {%4,%5,%6,%7}, {%8,%9}, {%0,%1,%2,%3};\n"
        : "+f"(C[0]), "+f"(C[1]), "+f"(C[2]), "+f"(C[3])
        : "r"(a0), "r"(a1), "r"(a2), "r"(a3), "r"(b0), "r"(b1));
}

__global__ void k_dummy() {}

// ---------------- init: zero states + sums + barriers -----------------------
__global__ void k_init() {
    int i = blockIdx.x * 256 + threadIdx.x;
    if (i < kB * kU) { g_H0[i] = 0.f; g_H1[i] = 0.f; }
    if (i < kM) g_S[i] = 0.f;
    if (i < 4) g_bar[i] = 0u;
}

// ---------------- Zx GEMM (tf32 mma, staged cvt): Z0 = emb[idx] @ W0x + b0 --
__global__ __launch_bounds__(512) void k_gemm_zx_tf32(
    const int* __restrict__ input_data, const float* __restrict__ emb,
    const float* __restrict__ W, const float* __restrict__ bias) {
    extern __shared__ uint32_t sm[];
    uint32_t* As = sm;                   // 2 buffers of 256x36 (tf32 bits)
    uint32_t* Bs = sm + 2 * 256 * 36;    // 2 buffers of 32x136
    __shared__ const float* rowp[256];
    float* Z = g_Z0x;
    const int tid = threadIdx.x;
    const int lane = tid & 31;
    const int w = tid >> 5;
    const int warpM = w & 7;
    const int warpN = w >> 3;
    const int m0 = blockIdx.y * 256;
    const int n0 = blockIdx.x * 128;
    const int r = lane >> 2, cq = lane & 3;

    if (tid < 256) {
        int m = m0 + tid;
        int t = m >> 6, b = m & 63;
        rowp[tid] = emb + (size_t)input_data[b * kT + t] * kU;
    }
    __syncthreads();

    float acc[2][8][4];
#pragma unroll
    for (int i = 0; i < 2; i++)
#pragma unroll
        for (int j = 0; j < 8; j++)
#pragma unroll
            for (int k = 0; k < 4; k++) acc[i][j][k] = 0.f;

    float4 ra[4], rb[2];
    auto loadG = [&](int kc) {
#pragma unroll
        for (int p = 0; p < 4; p++) {
            int e = p * 512 + tid;
            ra[p] = *(const float4*)&rowp[e >> 3][kc * 32 + (e & 7) * 4];
        }
#pragma unroll
        for (int p = 0; p < 2; p++) {
            int e = p * 512 + tid;
            rb[p] = *(const float4*)&W[(size_t)(kc * 32 + (e >> 5)) * kG + n0 + (e & 31) * 4];
        }
    };
    auto storeS = [&](int buf) {
        uint32_t* Ab = As + buf * 256 * 36;
        uint32_t* Bb = Bs + buf * 32 * 136;
#pragma unroll
        for (int p = 0; p < 4; p++) {
            int e = p * 512 + tid;
            uint4 v = make_uint4(f2tf32(ra[p].x), f2tf32(ra[p].y), f2tf32(ra[p].z), f2tf32(ra[p].w));
            *(uint4*)&Ab[(e >> 3) * 36 + (e & 7) * 4] = v;
        }
#pragma unroll
        for (int p = 0; p < 2; p++) {
            int e = p * 512 + tid;
            uint4 v = make_uint4(f2tf32(rb[p].x), f2tf32(rb[p].y), f2tf32(rb[p].z), f2tf32(rb[p].w));
            *(uint4*)&Bb[(e >> 5) * 136 + (e & 31) * 4] = v;
        }
    };

    loadG(0);
    storeS(0);
    __syncthreads();

    for (int kc = 0; kc < 8; kc++) {
        int buf = kc & 1;
        if (kc < 7) loadG(kc + 1);
        const uint32_t* Ab = As + buf * 256 * 36;
        const uint32_t* Bb = Bs + buf * 32 * 136;
#pragma unroll
        for (int kk = 0; kk < 4; kk++) {
            uint32_t af[2][4];
#pragma unroll
            for (int mi = 0; mi < 2; mi++) {
                const uint32_t* ap = &Ab[(warpM * 32 + mi * 16 + r) * 36 + kk * 8 + cq];
                af[mi][0] = ap[0];
                af[mi][1] = ap[8 * 36];
                af[mi][2] = ap[4];
                af[mi][3] = ap[8 * 36 + 4];
            }
#pragma unroll
            for (int ni = 0; ni < 8; ni++) {
                const uint32_t* bp = &Bb[(kk * 8 + cq) * 136 + warpN * 64 + ni * 8 + r];
                uint32_t b0 = bp[0];
                uint32_t b1 = bp[4 * 136];
#pragma unroll
                for (int mi = 0; mi < 2; mi++)
                    mma_tf32(acc[mi][ni], af[mi][0], af[mi][1], af[mi][2], af[mi][3], b0, b1);
            }
        }
        if (kc < 7) { storeS(buf ^ 1); __syncthreads(); }
    }

#pragma unroll
    for (int ni = 0; ni < 8; ni++) {
        int col = n0 + warpN * 64 + ni * 8 + cq * 2;
        float2 bb = *(const float2*)&bias[col];
#pragma unroll
        for (int mi = 0; mi < 2; mi++) {
            int gm = m0 + warpM * 32 + mi * 16 + r;
            *(float2*)&Z[(size_t)gm * kG + col] =
                make_float2(acc[mi][ni][0] + bb.x, acc[mi][ni][1] + bb.y);
            *(float2*)&Z[(size_t)(gm + 8) * kG + col] =
                make_float2(acc[mi][ni][2] + bb.x, acc[mi][ni][3] + bb.y);
        }
    }
}

// ---------------- pipelined 2-layer persistent LSTM, per-warp autonomy -----
// 128 blocks = 4 row-groups (16 rows) x 32 u-blocks (8 u). 512 threads.
// Warps 0..7: L0 k-slice (32 k); warps 8..15: L1 k-slice (64 k of 512).
// Per step, each warp: polls flag, LDGs ITS OWN disjoint h-slice, stages to
// private smem, mma with register-resident tf32 weights (hi+lo A split).
// Epilogue split: tid<128 -> L0 gates, tid 128..255 -> L1 gates.
// Partials double-buffered by step parity.
__global__ __launch_bounds__(512) void k_lstm_pipe(
    const float* __restrict__ W0, const float* __restrict__ W1,
    const float* __restrict__ b1v) {
    extern __shared__ float sms[];
    float* stg0 = sms;                  // 8 x (16 x 36)   L0 stages
    float* stg1 = sms + 8 * 576;        // 8 x (16 x 68)   L1 stages
    float* pbuf = stg1 + 8 * 1088;      // 2 x (4608 + 4608) partials

    const int tid = threadIdx.x;
    const int bx = blockIdx.x;
    const int rg = bx >> 5, ub = bx & 31;
    const int r0 = rg * 16;
    const int w = tid >> 5, lane = tid & 31;
    const int r = lane >> 2, cq = lane & 3;
    const int isL1 = (w >= 8);
    const int ksl = w & 7;
    const int nkt = isL1 ? 8 : 4;
    const int stride = isL1 ? 68 : 36;
    float* stg = isL1 ? (stg1 + (w - 8) * 1088) : (stg0 + w * 576);

    // ---- weight B-fragments in registers (once) ----
    uint32_t Bf[8][4][2];
    {
        const float* Wsrc = isL1 ? W1 : (W0 + (size_t)kU * kG);
        const int kstep = isL1 ? 64 : 32;
#pragma unroll
        for (int kt = 0; kt < 8; kt++) {
            if (kt < nkt) {
                int kg = ksl * kstep + kt * 8 + cq;
#pragma unroll
                for (int nt = 0; nt < 4; nt++) {
                    int c = nt * 8 + r;
                    int gcol = (c & 3) * kU + ub * 8 + (c >> 2);
                    Bf[kt][nt][0] = f2tf32(Wsrc[(size_t)kg * kG + gcol]);
                    Bf[kt][nt][1] = f2tf32(Wsrc[(size_t)(kg + 4) * kG + gcol]);
                }
            }
        }
    }
    const int kbase = isL1 ? ((ksl & 3) * 64) : (ksl * 32);
    const bool useH1 = isL1 && (ksl >= 4);

    // epilogue identity: et = tid & 127 -> (r8, u8); tid<128: L0, 128..255: L1
    const int et = tid & 127;
    const int r8 = et >> 3, u8 = et & 7;
    const int u0e = ub * 8 + u8;
    float c0 = 0.f, c1 = 0.f;
    float b1g[4];
    if (tid >= 128 && tid < 256) {
#pragma unroll
        for (int g = 0; g < 4; g++) b1g[g] = b1v[g * kU + u0e];
    }

    for (int t = 0; t <= kT; t++) {
        // prefetch z0x gates for L0-epilogue threads (independent of flag)
        float z0g[4];
        if (tid < 128 && t < kT) {
#pragma unroll
            for (int g = 0; g < 4; g++)
                z0g[g] = __ldg(&g_Z0x[(size_t)t * kB * kG + (size_t)(r0 + r8) * kG + g * kU + u0e]);
        }

        // ---- per-warp poll: wait for all 32 blocks of this rg to finish t-1
        if (t > 0) {
            unsigned goal = (unsigned)t * 32u, v;
            do {
                asm volatile("ld.acquire.gpu.u32 %0, [%1];" : "=r"(v) : "l"(&g_bar[rg]));
            } while (v < goal);
        }

        float* pb = pbuf + (t & 1) * 9216;
        float* pp = isL1 ? (pb + 4608) : pb;

        float C[4][4];
#pragma unroll
        for (int nt = 0; nt < 4; nt++)
#pragma unroll
            for (int j = 0; j < 4; j++) C[nt][j] = 0.f;

        const bool active = isL1 ? (t >= 1) : (t < kT);
        if (active) {
            const float* src = useH1 ? (g_H1 + (size_t)(t - 1) * kB * kU)
                                     : (g_H0 + (size_t)t * kB * kU);
            // ---- stage this warp's disjoint slice (coalesced LDG.128) ----
            if (!isL1) {
#pragma unroll
                for (int i = 0; i < 4; i++) {
                    int row = i * 4 + (lane >> 3);
                    float4 v = __ldg((const float4*)(src + (size_t)(r0 + row) * kU + kbase) + (lane & 7));
                    *(float4*)&stg[row * 36 + (lane & 7) * 4] = v;
                }
            } else {
#pragma unroll
                for (int i = 0; i < 8; i++) {
                    int row = i * 2 + (lane >> 4);
                    float4 v = __ldg((const float4*)(src + (size_t)(r0 + row) * kU + kbase) + (lane & 15));
                    *(float4*)&stg[row * 68 + (lane & 15) * 4] = v;
                }
            }
            __syncwarp();
            // ---- mma: LDS fragments, hi/lo tf32 split in registers ----
#pragma unroll
            for (int kt = 0; kt < 8; kt++) {
                if (kt < nkt) {
                    int ka = kt * 8 + cq;
                    float f0 = stg[r * stride + ka];
                    float f1 = stg[(r + 8) * stride + ka];
                    float f2 = stg[r * stride + ka + 4];
                    float f3 = stg[(r + 8) * stride + ka + 4];
                    uint32_t h0 = f2tf32(f0), h1 = f2tf32(f1);
                    uint32_t h2 = f2tf32(f2), h3 = f2tf32(f3);
                    uint32_t l0 = f2tf32(f0 - __uint_as_float(h0));
                    uint32_t l1 = f2tf32(f1 - __uint_as_float(h1));
                    uint32_t l2 = f2tf32(f2 - __uint_as_float(h2));
                    uint32_t l3 = f2tf32(f3 - __uint_as_float(h3));
#pragma unroll
                    for (int nt = 0; nt < 4; nt++) {
                        mma_tf32(C[nt], h0, h1, h2, h3, Bf[kt][nt][0], Bf[kt][nt][1]);
                        mma_tf32(C[nt], l0, l1, l2, l3, Bf[kt][nt][0], Bf[kt][nt][1]);
                    }
                }
            }
        }
        // ---- store partials (zeros when inactive) ----
#pragma unroll
        for (int nt = 0; nt < 4; nt++) {
            *(float2*)&pp[(ksl * 16 + r) * 36 + nt * 8 + 2 * cq] = make_float2(C[nt][0], C[nt][1]);
            *(float2*)&pp[(ksl * 16 + r + 8) * 36 + nt * 8 + 2 * cq] = make_float2(C[nt][2], C[nt][3]);
        }
        __syncthreads();

        // ---- split epilogue: L0 on tid<128, L1 on tid 128..255 ----
        if (tid < 128) {
            if (t < kT) {
                float4 s = make_float4(0.f, 0.f, 0.f, 0.f);
#pragma unroll
                for (int k = 0; k < 8; k++) {
                    float4 p = *(const float4*)&pb[(k * 16 + r8) * 36 + u8 * 4];
                    s.x += p.x; s.y += p.y; s.z += p.z; s.w += p.w;
                }
                float zi = z0g[0] + s.x, zj = z0g[1] + s.y;
                float zf = z0g[2] + s.z, zo = z0g[3] + s.w;
                float inj = sigmoidf_(zi) * tanhf(zj);
                c0 = c0 * sigmoidf_(zf + 1.f) + inj;     // FORGET_BIAS = 1
                g_H0[(size_t)(t + 1) * kB * kU + (size_t)(r0 + r8) * kU + u0e] =
                    tanhf(c0) * sigmoidf_(zo);
            }
        } else if (tid < 256) {
            if (t >= 1) {
                const float* p1 = pb + 4608;
                float4 s = make_float4(0.f, 0.f, 0.f, 0.f);
#pragma unroll
                for (int k = 0; k < 8; k++) {
                    float4 p = *(const float4*)&p1[(k * 16 + r8) * 36 + u8 * 4];
                    s.x += p.x; s.y += p.y; s.z += p.z; s.w += p.w;
                }
                float zi = b1g[0] + s.x, zj = b1g[1] + s.y;
                float zf = b1g[2] + s.z, zo = b1g[3] + s.w;
                float inj = sigmoidf_(zi) * tanhf(zj);
                c1 = c1 * sigmoidf_(zf + 1.f) + inj;
                g_H1[(size_t)t * kB * kU + (size_t)(r0 + r8) * kU + u0e] =
                    tanhf(c1) * sigmoidf_(zo);
            }
        }
        // arrival: epilogue warps (0..7) sync then tid0 releases
        if (tid < 256) {
            asm volatile("bar.sync 1, 256;" ::: "memory");
            if (tid == 0 && t < kT) {
                asm volatile("red.release.gpu.global.add.u32 [%0], %1;"
                             :: "l"(&g_bar[rg]), "r"(1u) : "memory");
            }
        }
    }
}

// ---------------- fused logits GEMM (tf32 mma, staged cvt) -----------------
__global__ __launch_bounds__(512) void k_logits_tf32(
    const int* __restrict__ targets, const float* __restrict__ SW,
    const float* __restrict__ sb) {
    extern __shared__ uint32_t sm[];
    uint32_t* As = sm;                   // 2 buffers of 256x36
    uint32_t* Bs = sm + 2 * 256 * 36;    // 2 buffers of 32x136
    const float* __restrict__ A = g_H1 + kB * kU;
    const int tid = threadIdx.x;
    const int lane = tid & 31;
    const int w = tid >> 5;
    const int warpM = w & 7;
    const int warpN = w >> 3;
    const int m0 = blockIdx.y * 256;
    const int n0 = blockIdx.x * 128;
    const int r = lane >> 2, cq = lane & 3;

    float acc[2][8][4];
#pragma unroll
    for (int i = 0; i < 2; i++)
#pragma unroll
        for (int j = 0; j < 8; j++)
#pragma unroll
            for (int k = 0; k < 4; k++) acc[i][j][k] = 0.f;

    float4 ra[4], rb[2];
    auto loadG = [&](int kc) {
#pragma unroll
        for (int p = 0; p < 4; p++) {
            int e = p * 512 + tid;
            ra[p] = *(const float4*)&A[(size_t)(m0 + (e >> 3)) * kU + kc * 32 + (e & 7) * 4];
        }
#pragma unroll
        for (int p = 0; p < 2; p++) {
            int e = p * 512 + tid;
            rb[p] = *(const float4*)&SW[(size_t)(kc * 32 + (e >> 5)) * kV + n0 + (e & 31) * 4];
        }
    };
    auto storeS = [&](int buf) {
        uint32_t* Ab = As + buf * 256 * 36;
        uint32_t* Bb = Bs + buf * 32 * 136;
#pragma unroll
        for (int p = 0; p < 4; p++) {
            int e = p * 512 + tid;
            uint4 v = make_uint4(f2tf32(ra[p].x), f2tf32(ra[p].y), f2tf32(ra[p].z), f2tf32(ra[p].w));
            *(uint4*)&Ab[(e >> 3) * 36 + (e & 7) * 4] = v;
        }
#pragma unroll
        for (int p = 0; p < 2; p++) {
            int e = p * 512 + tid;
            uint4 v = make_uint4(f2tf32(rb[p].x), f2tf32(rb[p].y), f2tf32(rb[p].z), f2tf32(rb[p].w));
            *(uint4*)&Bb[(e >> 5) * 136 + (e & 31) * 4] = v;
        }
    };

    loadG(0);
    storeS(0);
    __syncthreads();

    for (int kc = 0; kc < 8; kc++) {
        int buf = kc & 1;
        if (kc < 7) loadG(kc + 1);
        const uint32_t* Ab = As + buf * 256 * 36;
        const uint32_t* Bb = Bs + buf * 32 * 136;
#pragma unroll
        for (int kk = 0; kk < 4; kk++) {
            uint32_t af[2][4];
#pragma unroll
            for (int mi = 0; mi < 2; mi++) {
                const uint32_t* ap = &Ab[(warpM * 32 + mi * 16 + r) * 36 + kk * 8 + cq];
                af[mi][0] = ap[0];
                af[mi][1] = ap[8 * 36];
                af[mi][2] = ap[4];
                af[mi][3] = ap[8 * 36 + 4];
            }
#pragma unroll
            for (int ni = 0; ni < 8; ni++) {
                const uint32_t* bp = &Bb[(kk * 8 + cq) * 136 + warpN * 64 + ni * 8 + r];
                uint32_t b0 = bp[0];
                uint32_t b1 = bp[4 * 136];
#pragma unroll
                for (int mi = 0; mi < 2; mi++)
                    mma_tf32(acc[mi][ni], af[mi][0], af[mi][1], af[mi][2], af[mi][3], b0, b1);
            }
        }
        if (kc < 7) { storeS(buf ^ 1); __syncthreads(); }
    }

#pragma unroll
    for (int mi = 0; mi < 2; mi++) {
#pragma unroll
        for (int hh = 0; hh < 2; hh++) {
            int gm = m0 + warpM * 32 + mi * 16 + r + 8 * hh;
            int tt = gm >> 6, bb = gm & 63;
            int tg = targets[bb * kT + tt];
            float s = 0.f;
#pragma unroll
            for (int ni = 0; ni < 8; ni++) {
                int col = n0 + warpN * 64 + ni * 8 + cq * 2;
                float l0 = acc[mi][ni][hh * 2 + 0] + sb[col];
                float l1 = acc[mi][ni][hh * 2 + 1] + sb[col + 1];
                if (col == tg) g_TL[gm] = l0;
                if (col + 1 == tg) g_TL[gm] = l1;
                s += __expf(l0) + __expf(l1);
            }
            s += __shfl_xor_sync(0xffffffffu, s, 1);
            s += __shfl_xor_sync(0xffffffffu, s, 2);
            if (cq == 0) atomicAdd(&g_S[gm], s);
        }
    }
}

// ---------------- final: cost = mean(log(S) - target_logit) ----------------
__global__ void k_final(float* __restrict__ out) {
    __shared__ float red[256];
    int tid = threadIdx.x;
    float acc = 0.f;
    for (int rr = tid; rr < kM; rr += 256) acc += logf(g_S[rr]) - g_TL[rr];
    red[tid] = acc;
    __syncthreads();
    for (int s = 128; s > 0; s >>= 1) {
        if (tid < s) red[tid] += red[tid + s];
        __syncthreads();
    }
    if (tid == 0) out[0] = red[0] / (float)kM;
}

// ---------------- launch ----------------------------------------------------
extern "C" void kernel_launch(void* const* d_in, const int* in_sizes, int n_in,
                              void* d_out, int out_size) {
    const int*   input_data = (const int*)d_in[0];
    const int*   targets    = (const int*)d_in[1];
    const float* emb        = (const float*)d_in[2];
    const float* W0         = (const float*)d_in[3];
    const float* b0         = (const float*)d_in[4];
    const float* W1         = (const float*)d_in[5];
    const float* b1         = (const float*)d_in[6];
    const float* sw         = (const float*)d_in[7];
    const float* sb         = (const float*)d_in[8];
    float* out = (float*)d_out;

    const int pipe_smem = (8 * 576 + 8 * 1088 + 2 * 9216) * 4;   // 126976 B
    const int gemm_smem = (2 * 256 * 36 + 2 * 32 * 136) * 4;     // 108544 B
    cudaFuncSetAttribute(k_lstm_pipe, cudaFuncAttributeMaxDynamicSharedMemorySize, pipe_smem);
    cudaFuncSetAttribute(k_gemm_zx_tf32, cudaFuncAttributeMaxDynamicSharedMemorySize, gemm_smem);
    cudaFuncSetAttribute(k_logits_tf32, cudaFuncAttributeMaxDynamicSharedMemorySize, gemm_smem);

    // k_lstm_pipe at launch index 3 — ncu's capture slot
    k_init<<<64, 256>>>();                                                    // 0
    k_gemm_zx_tf32<<<dim3(8, 32), 512, gemm_smem>>>(input_data, emb, W0, b0); // 1
    k_dummy<<<1, 32>>>();                                                     // 2
    k_lstm_pipe<<<128, 512, pipe_smem>>>(W0, W1, b1);                         // 3
    k_logits_tf32<<<dim3(125, 32), 512, gemm_smem>>>(targets, sw, sb);        // 4
    k_final<<<1, 256>>>(out);                                                 // 5
}